// round 10
// baseline (speedup 1.0000x reference)
#include <cuda_runtime.h>
#include <cstdint>

// ---------------- scratch (no allocations allowed) ----------------
#define B_ 16
#define C_ 21
#define D_ 512
#define HW_ 4096          // 64*64
#define LW_ 513
#define NV_ 336           // B_*C_ proto rows
#define GR_ 352           // padded to 11*32
#define KZ_ 2             // K-split factor (512/256)

__device__ unsigned char g_lab[B_ * HW_];            // resized labels as u8
__device__ int           g_pres[B_ * C_];            // class present in image (0/1)
__device__ float         g_sums[B_ * C_ * D_];       // pooled (unnormalized) sums
__device__ float         g_Spart[KZ_ * GR_ * GR_];   // partial Grams per K chunk
__device__ float         g_normsq[NV_];              // squared norms (k4a epilogue atomics)
__device__ float         g_pAll[C_ * C_];            // sum exp(S-10) per (c,e) block
__device__ float         g_pPos[C_];                 // sum of valid diag S values
__device__ int           g_pCnt[C_];                 // count of valid diag entries

// ---------------- K1: bilinear resize (half-pixel, exact) + presence ----------------
// grid (16,16), 256 threads: one pixel per thread
__global__ void k1_resize(const int* __restrict__ labels) {
    int b = blockIdx.x;
    const int* L = labels + (size_t)b * LW_ * LW_;
    int p = blockIdx.y * 256 + threadIdx.x;
    int y = p >> 6, x = p & 63;
    // src = (i+0.5)*513/64 - 0.5 ; exact in fp32 (multiples of 1/128)
    float sy = (y + 0.5f) * 8.015625f - 0.5f;
    float sx = (x + 0.5f) * 8.015625f - 0.5f;
    int y0 = (int)sy; float wy = sy - (float)y0;
    int x0 = (int)sx; float wx = sx - (float)x0;
    const int* r0 = L + y0 * LW_ + x0;
    const int* r1 = r0 + LW_;
    float v00 = (float)r0[0], v01 = (float)r0[1];
    float v10 = (float)r1[0], v11 = (float)r1[1];
    float v = (1.0f - wy) * ((1.0f - wx) * v00 + wx * v01)
            +          wy * ((1.0f - wx) * v10 + wx * v11);
    int c = (int)v;   // truncation; v exact
    g_lab[b * HW_ + p] = (unsigned char)c;
    g_pres[b * C_ + c] = 1;      // benign race
}

// ---------------- K2: masked per-class pooling (the 134 MB pass) ----------------
// grid (16, 64), 256 threads; warp w handles channel d = dt*8 + w, fully independent.
// Per-warp private bins [21 classes][32 lanes], stride 32 -> scatter bank = lane.
__global__ __launch_bounds__(256) void k2_pool(const float* __restrict__ feat) {
    int b   = blockIdx.x;
    int dt  = blockIdx.y;
    int tid = threadIdx.x;
    int w = tid >> 5, lane = tid & 31;

    __shared__ unsigned char slab[HW_];
    __shared__ float bins[8 * C_ * 32];

    ((uint4*)slab)[tid] = ((const uint4*)(g_lab + b * HW_))[tid];
    __syncthreads();

    int d = dt * 8 + w;
    float* bw = bins + w * (C_ * 32);

    #pragma unroll
    for (int c = 0; c < C_; c++) bw[c * 32 + lane] = 0.0f;

    const float4* F = (const float4*)(feat + ((size_t)(b * D_ + d)) * HW_);
    #pragma unroll 8
    for (int k = 0; k < 32; k++) {
        int p4 = k * 32 + lane;
        float4 f = __ldcs(&F[p4]);
        uchar4 lc = ((const uchar4*)slab)[p4];
        bw[lc.x * 32 + lane] += f.x;
        bw[lc.y * 32 + lane] += f.y;
        bw[lc.z * 32 + lane] += f.z;
        bw[lc.w * 32 + lane] += f.w;
    }
    __syncwarp();

    // lane c (<21) sums class c's 32 columns; XOR-rotated reads -> conflict-free
    if (lane < C_) {
        float s = 0.0f;
        #pragma unroll
        for (int m = 0; m < 32; m++)
            s += bw[lane * 32 + ((m + lane) & 31)];
        g_sums[((size_t)(b * C_ + lane)) * D_ + d] = s;
    }
}

// ---------------- K4a: partial Gram SGEMM  U_z = S_z * S_z^T ----------------
// grid (11,11,2), 128 threads. 32x32 tile, 4x2 per thread, K chunk = 256 (2 stages).
// Diagonal tiles also accumulate squared norms into g_normsq via atomics.
__global__ __launch_bounds__(128) void k4a_gemm() {
    __shared__ float4 As4[32][32];   // [row][k4]
    __shared__ float4 Bs4[32][32];   // [k4][col]

    int t = threadIdx.x;
    int tr = t >> 4;
    int tc = t & 15;
    int rowBase = blockIdx.y * 32;
    int colBase = blockIdx.x * 32;
    int kz = blockIdx.z;              // K half (64 f4)

    float acc[4][2];
    #pragma unroll
    for (int r = 0; r < 4; r++) { acc[r][0] = 0.f; acc[r][1] = 0.f; }

    const float4* P4 = (const float4*)g_sums;   // row stride 128 f4

    #pragma unroll
    for (int kc = 0; kc < 2; kc++) {            // two 32-f4 stages per K half
        int kOff = kz * 64 + kc * 32;
        #pragma unroll
        for (int m = 0; m < 8; m++) {
            int idx = m * 128 + t;
            int row = idx >> 5, q = idx & 31;
            int v = rowBase + row;
            As4[row][q] = (v < NV_) ? P4[(size_t)v * 128 + kOff + q]
                                    : make_float4(0.f, 0.f, 0.f, 0.f);
        }
        #pragma unroll
        for (int m = 0; m < 8; m++) {
            int idx = m * 128 + t;
            int row = idx >> 5, q = idx & 31;
            int v = colBase + row;
            Bs4[q][row] = (v < NV_) ? P4[(size_t)v * 128 + kOff + q]
                                    : make_float4(0.f, 0.f, 0.f, 0.f);
        }
        __syncthreads();

        #pragma unroll 8
        for (int k4 = 0; k4 < 32; k4++) {
            float4 b0 = Bs4[k4][tc];
            float4 b1 = Bs4[k4][tc + 16];
            #pragma unroll
            for (int r = 0; r < 4; r++) {
                float4 a = As4[tr * 4 + r][k4];
                acc[r][0] = fmaf(a.x, b0.x, fmaf(a.y, b0.y, fmaf(a.z, b0.z, fmaf(a.w, b0.w, acc[r][0]))));
                acc[r][1] = fmaf(a.x, b1.x, fmaf(a.y, b1.y, fmaf(a.z, b1.z, fmaf(a.w, b1.w, acc[r][1]))));
            }
        }
        __syncthreads();
    }

    float* out = g_Spart + (size_t)kz * GR_ * GR_;
    #pragma unroll
    for (int r = 0; r < 4; r++) {
        int v = rowBase + tr * 4 + r;
        out[(size_t)v * GR_ + colBase + tc]      = acc[r][0];
        out[(size_t)v * GR_ + colBase + tc + 16] = acc[r][1];
    }

    // diagonal tile: accumulate squared norms (each diag element hit once per kz)
    if (rowBase == colBase) {
        #pragma unroll
        for (int r = 0; r < 4; r++) {
            int rl = tr * 4 + r;
            int v = rowBase + rl;
            if (v < NV_) {
                if (rl == tc)      atomicAdd(&g_normsq[v], acc[r][0]);
                if (rl == tc + 16) atomicAdd(&g_normsq[v], acc[r][1]);
            }
        }
    }
}

// ---------------- K4b: per-(c,e) block exp-sum reduce (no prologue) ----------------
__global__ __launch_bounds__(256) void k4b_reduce() {
    int c = blockIdx.x / C_;
    int e = blockIdx.x % C_;
    int tid = threadIdx.x;
    int i = tid >> 4;
    int j = tid & 15;
    int vi = i * C_ + c, vj = j * C_ + e;

    float u = g_Spart[(size_t)vi * GR_ + vj]
            + g_Spart[(size_t)GR_ * GR_ + (size_t)vi * GR_ + vj];
    float rni = 1.0f / fmaxf(sqrtf(g_normsq[vi]), 1e-12f);
    float rnj = 1.0f / fmaxf(sqrtf(g_normsq[vj]), 1e-12f);
    float dot = u * rni * rnj;

    bool valid = (g_pres[vi] != 0) && (g_pres[vj] != 0);
    float s    = dot * 10.0f;                       // / T
    float term = valid ? expf(s - 10.0f) : 0.0f;    // shift by 1/T (max possible)

    #pragma unroll
    for (int o = 16; o > 0; o >>= 1)
        term += __shfl_xor_sync(0xffffffffu, term, o);

    __shared__ float wt[8], wp[8], wc[8];
    int warp = tid >> 5;
    bool diagBlk = (e == c);                        // uniform per block

    if (diagBlk) {
        float pos  = valid ? s : 0.0f;
        float cntv = valid ? 1.0f : 0.0f;
        #pragma unroll
        for (int o = 16; o > 0; o >>= 1) {
            pos  += __shfl_xor_sync(0xffffffffu, pos, o);
            cntv += __shfl_xor_sync(0xffffffffu, cntv, o);
        }
        if ((tid & 31) == 0) { wp[warp] = pos; wc[warp] = cntv; }
    }
    if ((tid & 31) == 0) wt[warp] = term;
    __syncthreads();
    if (tid == 0) {
        float T = 0.f;
        #pragma unroll
        for (int w = 0; w < 8; w++) T += wt[w];
        g_pAll[blockIdx.x] = T;
        if (diagBlk) {
            float P = 0.f, Cn = 0.f;
            #pragma unroll
            for (int w = 0; w < 8; w++) { P += wp[w]; Cn += wc[w]; }
            g_pPos[c] = P; g_pCnt[c] = (int)(Cn + 0.5f);
        }
    }
}

// ---------------- K5: per-class loss + total ----------------
__global__ void k5_final(float* __restrict__ out) {
    int c = threadIdx.x;
    float loss_c = 0.0f;
    if (c < C_) {
        bool present = false;
        #pragma unroll
        for (int b = 0; b < B_; b++) present = present || (g_pres[b * C_ + c] != 0);
        if (present) {
            float sAll = 0.0f;
            #pragma unroll
            for (int e = 0; e < C_; e++) sAll += g_pAll[c * C_ + e];
            float sDiag = g_pAll[c * C_ + c];
            float lse = 10.0f + logf(sAll + sDiag);
            int cnt = g_pCnt[c];
            float pm = g_pPos[c] / (float)(cnt > 1 ? cnt : 1);
            loss_c = lse - pm;
        }
    }
    #pragma unroll
    for (int o = 16; o > 0; o >>= 1) loss_c += __shfl_xor_sync(0xffffffffu, loss_c, o);
    if (threadIdx.x == 0) out[0] = loss_c;
}

// ---------------- launch ----------------
extern "C" void kernel_launch(void* const* d_in, const int* in_sizes, int n_in,
                              void* d_out, int out_size) {
    const float* features = (const float*)d_in[0];   // [16,512,64,64] fp32
    const int*   labels   = (const int*)d_in[1];     // [16,513,513] int32
    float* out = (float*)d_out;

    void* presPtr = nullptr;
    cudaGetSymbolAddress(&presPtr, g_pres);
    cudaMemsetAsync(presPtr, 0, B_ * C_ * sizeof(int));
    void* nsqPtr = nullptr;
    cudaGetSymbolAddress(&nsqPtr, g_normsq);
    cudaMemsetAsync(nsqPtr, 0, NV_ * sizeof(float));

    k1_resize<<<dim3(B_, 16), 256>>>(labels);
    k2_pool<<<dim3(B_, D_ / 8), 256>>>(features);
    k4a_gemm<<<dim3(11, 11, KZ_), 128>>>();
    k4b_reduce<<<C_ * C_, 256>>>();
    k5_final<<<1, 32>>>(out);
}

// round 11
// speedup vs baseline: 1.0012x; 1.0012x over previous
#include <cuda_runtime.h>
#include <cstdint>

// ---------------- scratch (no allocations allowed) ----------------
#define B_ 16
#define C_ 21
#define D_ 512
#define HW_ 4096          // 64*64
#define LW_ 513
#define NV_ 336           // B_*C_ proto rows
#define GR_ 352           // padded to 11*32
#define KZ_ 2             // K-split factor (512/256)

__device__ unsigned char g_lab[B_ * HW_];            // resized labels as u8
__device__ int           g_pres[B_ * C_];            // class present in image (0/1)
__device__ float         g_sums[B_ * C_ * D_];       // pooled (unnormalized) sums
__device__ float         g_Spart[KZ_ * GR_ * GR_];   // partial Grams per K chunk
__device__ float         g_normsq[NV_];              // squared norms (k4a epilogue atomics)
__device__ float         g_pAll[C_ * C_];            // sum exp(S-10) per (c,e) block
__device__ float         g_pPos[C_];                 // sum of valid diag S values
__device__ int           g_pCnt[C_];                 // count of valid diag entries
__device__ int           g_done;                     // completion counter (reset device-side)

// ---------------- K1: bilinear resize (half-pixel, exact) + presence ----------------
// grid (16, 8), 256 threads: block handles 512 pixels of image b
__global__ void k1_resize(const int* __restrict__ labels) {
    int b = blockIdx.x;
    const int* L = labels + (size_t)b * LW_ * LW_;
    int base = blockIdx.y * 512;
    #pragma unroll
    for (int q = 0; q < 2; q++) {
        int p = base + q * 256 + threadIdx.x;
        int y = p >> 6, x = p & 63;
        // src = (i+0.5)*513/64 - 0.5 ; exact in fp32 (multiples of 1/128)
        float sy = (y + 0.5f) * 8.015625f - 0.5f;
        float sx = (x + 0.5f) * 8.015625f - 0.5f;
        int y0 = (int)sy; float wy = sy - (float)y0;
        int x0 = (int)sx; float wx = sx - (float)x0;
        const int* r0 = L + y0 * LW_ + x0;
        const int* r1 = r0 + LW_;
        float v00 = (float)r0[0], v01 = (float)r0[1];
        float v10 = (float)r1[0], v11 = (float)r1[1];
        float v = (1.0f - wy) * ((1.0f - wx) * v00 + wx * v01)
                +          wy * ((1.0f - wx) * v10 + wx * v11);
        int c = (int)v;   // truncation; v exact
        g_lab[b * HW_ + p] = (unsigned char)c;
        g_pres[b * C_ + c] = 1;      // benign race
    }
}

// ---------------- K2: masked per-class pooling (the 134 MB pass) ----------------
// grid (16, 64), 256 threads; warp w handles channel d = dt*8 + w, fully independent.
__global__ __launch_bounds__(256) void k2_pool(const float* __restrict__ feat) {
    int b   = blockIdx.x;
    int dt  = blockIdx.y;
    int tid = threadIdx.x;
    int w = tid >> 5, lane = tid & 31;

    __shared__ unsigned char slab[HW_];
    __shared__ float bins[8 * C_ * 32];

    ((uint4*)slab)[tid] = ((const uint4*)(g_lab + b * HW_))[tid];
    __syncthreads();

    int d = dt * 8 + w;
    float* bw = bins + w * (C_ * 32);

    #pragma unroll
    for (int c = 0; c < C_; c++) bw[c * 32 + lane] = 0.0f;

    const float4* F = (const float4*)(feat + ((size_t)(b * D_ + d)) * HW_);
    #pragma unroll 8
    for (int k = 0; k < 32; k++) {
        int p4 = k * 32 + lane;
        float4 f = __ldcs(&F[p4]);
        uchar4 lc = ((const uchar4*)slab)[p4];
        bw[lc.x * 32 + lane] += f.x;
        bw[lc.y * 32 + lane] += f.y;
        bw[lc.z * 32 + lane] += f.z;
        bw[lc.w * 32 + lane] += f.w;
    }
    __syncwarp();

    // lane c (<21) sums class c's 32 columns; XOR-rotated reads -> conflict-free
    if (lane < C_) {
        float s = 0.0f;
        #pragma unroll
        for (int m = 0; m < 32; m++)
            s += bw[lane * 32 + ((m + lane) & 31)];
        g_sums[((size_t)(b * C_ + lane)) * D_ + d] = s;
    }
}

// ---------------- K4a: partial Gram SGEMM  U_z = S_z * S_z^T ----------------
// grid (11,11,2), 128 threads. 32x32 tile, 4x2 per thread, K chunk = 256 (2 stages).
// Diagonal tiles accumulate squared norms into g_normsq (2-way fp atomics: commutative).
__global__ __launch_bounds__(128) void k4a_gemm() {
    __shared__ float4 As4[32][32];   // [row][k4]
    __shared__ float4 Bs4[32][32];   // [k4][col]

    int t = threadIdx.x;
    int tr = t >> 4;
    int tc = t & 15;
    int rowBase = blockIdx.y * 32;
    int colBase = blockIdx.x * 32;
    int kz = blockIdx.z;

    float acc[4][2];
    #pragma unroll
    for (int r = 0; r < 4; r++) { acc[r][0] = 0.f; acc[r][1] = 0.f; }

    const float4* P4 = (const float4*)g_sums;   // row stride 128 f4

    #pragma unroll
    for (int kc = 0; kc < 2; kc++) {
        int kOff = kz * 64 + kc * 32;
        #pragma unroll
        for (int m = 0; m < 8; m++) {
            int idx = m * 128 + t;
            int row = idx >> 5, q = idx & 31;
            int v = rowBase + row;
            As4[row][q] = (v < NV_) ? P4[(size_t)v * 128 + kOff + q]
                                    : make_float4(0.f, 0.f, 0.f, 0.f);
        }
        #pragma unroll
        for (int m = 0; m < 8; m++) {
            int idx = m * 128 + t;
            int row = idx >> 5, q = idx & 31;
            int v = colBase + row;
            Bs4[q][row] = (v < NV_) ? P4[(size_t)v * 128 + kOff + q]
                                    : make_float4(0.f, 0.f, 0.f, 0.f);
        }
        __syncthreads();

        #pragma unroll 8
        for (int k4 = 0; k4 < 32; k4++) {
            float4 b0 = Bs4[k4][tc];
            float4 b1 = Bs4[k4][tc + 16];
            #pragma unroll
            for (int r = 0; r < 4; r++) {
                float4 a = As4[tr * 4 + r][k4];
                acc[r][0] = fmaf(a.x, b0.x, fmaf(a.y, b0.y, fmaf(a.z, b0.z, fmaf(a.w, b0.w, acc[r][0]))));
                acc[r][1] = fmaf(a.x, b1.x, fmaf(a.y, b1.y, fmaf(a.z, b1.z, fmaf(a.w, b1.w, acc[r][1]))));
            }
        }
        __syncthreads();
    }

    float* out = g_Spart + (size_t)kz * GR_ * GR_;
    #pragma unroll
    for (int r = 0; r < 4; r++) {
        int v = rowBase + tr * 4 + r;
        out[(size_t)v * GR_ + colBase + tc]      = acc[r][0];
        out[(size_t)v * GR_ + colBase + tc + 16] = acc[r][1];
    }

    if (rowBase == colBase) {
        #pragma unroll
        for (int r = 0; r < 4; r++) {
            int rl = tr * 4 + r;
            int v = rowBase + rl;
            if (v < NV_) {
                if (rl == tc)      atomicAdd(&g_normsq[v], acc[r][0]);
                if (rl == tc + 16) atomicAdd(&g_normsq[v], acc[r][1]);
            }
        }
    }
}

// ---------------- K4b: 3 cells/block exp-sum reduce + fused final loss ----------------
// grid 147 blocks x 768 threads; sub-cell s = tid/256 handles cell = bid*3+s.
// Last finishing block computes the total loss and resets g_done.
__global__ __launch_bounds__(768) void k4b_loss(float* __restrict__ out) {
    int tid  = threadIdx.x;
    int sub  = tid >> 8;            // 0..2
    int ctid = tid & 255;
    int cell = blockIdx.x * 3 + sub;   // 0..440
    int c = cell / C_;
    int e = cell - c * C_;
    int i = ctid >> 4;
    int j = ctid & 15;
    int vi = i * C_ + c, vj = j * C_ + e;

    float u = g_Spart[(size_t)vi * GR_ + vj]
            + g_Spart[(size_t)GR_ * GR_ + (size_t)vi * GR_ + vj];
    float rni = 1.0f / fmaxf(sqrtf(g_normsq[vi]), 1e-12f);
    float rnj = 1.0f / fmaxf(sqrtf(g_normsq[vj]), 1e-12f);
    float dot = u * rni * rnj;

    bool valid = (g_pres[vi] != 0) && (g_pres[vj] != 0);
    float s    = dot * 10.0f;                       // / T
    float term = valid ? expf(s - 10.0f) : 0.0f;    // shift by 1/T

    #pragma unroll
    for (int o = 16; o > 0; o >>= 1)
        term += __shfl_xor_sync(0xffffffffu, term, o);

    __shared__ float wt[24], wp[24], wc[24];
    int warp = tid >> 5;                            // 0..23 ; cell warps = sub*8..sub*8+7
    bool diagBlk = (e == c);                        // uniform per sub-cell

    if (diagBlk) {
        float pos  = valid ? s : 0.0f;
        float cntv = valid ? 1.0f : 0.0f;
        #pragma unroll
        for (int o = 16; o > 0; o >>= 1) {
            pos  += __shfl_xor_sync(0xffffffffu, pos, o);
            cntv += __shfl_xor_sync(0xffffffffu, cntv, o);
        }
        if ((tid & 31) == 0) { wp[warp] = pos; wc[warp] = cntv; }
    }
    if ((tid & 31) == 0) wt[warp] = term;
    __syncthreads();

    if (ctid == 0) {
        float T = 0.f;
        #pragma unroll
        for (int w = 0; w < 8; w++) T += wt[sub * 8 + w];
        g_pAll[cell] = T;
        if (diagBlk) {
            float P = 0.f, Cn = 0.f;
            #pragma unroll
            for (int w = 0; w < 8; w++) { P += wp[sub * 8 + w]; Cn += wc[sub * 8 + w]; }
            g_pPos[c] = P; g_pCnt[c] = (int)(Cn + 0.5f);
        }
        __threadfence();
    }
    __syncthreads();

    // completion counter: last block computes the final loss
    __shared__ int lastFlag;
    if (tid == 0) {
        int prev = atomicAdd(&g_done, 1);
        lastFlag = (prev == gridDim.x - 1) ? 1 : 0;
    }
    __syncthreads();

    if (lastFlag) {
        float loss_c = 0.0f;
        int cc = tid;
        if (cc < C_) {
            bool present = false;
            #pragma unroll
            for (int b = 0; b < B_; b++) present = present || (g_pres[b * C_ + cc] != 0);
            if (present) {
                float sAll = 0.0f;
                #pragma unroll
                for (int ee = 0; ee < C_; ee++) sAll += g_pAll[cc * C_ + ee];
                float sDiag = g_pAll[cc * C_ + cc];
                float lse = 10.0f + logf(sAll + sDiag);
                int cnt = g_pCnt[cc];
                float pm = g_pPos[cc] / (float)(cnt > 1 ? cnt : 1);
                loss_c = lse - pm;
            }
        }
        if (tid < 32) {
            #pragma unroll
            for (int o = 16; o > 0; o >>= 1)
                loss_c += __shfl_xor_sync(0xffffffffu, loss_c, o);
            if (tid == 0) {
                out[0] = loss_c;
                g_done = 0;      // reset for next graph replay
            }
        }
    }
}

// ---------------- launch ----------------
extern "C" void kernel_launch(void* const* d_in, const int* in_sizes, int n_in,
                              void* d_out, int out_size) {
    const float* features = (const float*)d_in[0];   // [16,512,64,64] fp32
    const int*   labels   = (const int*)d_in[1];     // [16,513,513] int32
    float* out = (float*)d_out;

    void* presPtr = nullptr;
    cudaGetSymbolAddress(&presPtr, g_pres);
    cudaMemsetAsync(presPtr, 0, B_ * C_ * sizeof(int));
    void* nsqPtr = nullptr;
    cudaGetSymbolAddress(&nsqPtr, g_normsq);
    cudaMemsetAsync(nsqPtr, 0, NV_ * sizeof(float));

    k1_resize<<<dim3(B_, 8), 256>>>(labels);
    k2_pool<<<dim3(B_, D_ / 8), 256>>>(features);
    k4a_gemm<<<dim3(11, 11, KZ_), 128>>>();
    k4b_loss<<<147, 768>>>(out);
}

// round 12
// speedup vs baseline: 1.0836x; 1.0822x over previous
#include <cuda_runtime.h>
#include <cstdint>

// ---------------- scratch (no allocations allowed) ----------------
#define B_ 16
#define C_ 21
#define D_ 512
#define HW_ 4096          // 64*64
#define LW_ 513
#define NV_ 336           // B_*C_ proto rows
#define GR_ 352           // padded to 11*32
#define KZ_ 2             // K-split factor (512/256)

__device__ unsigned char g_lab[B_ * HW_];            // resized labels as u8
__device__ float         g_sums[B_ * C_ * D_];       // pooled (unnormalized) sums
__device__ float         g_Spart[KZ_ * GR_ * GR_];   // partial Grams per K chunk
__device__ float         g_normsq[NV_];              // squared norms (k4a epilogue atomics)
__device__ float         g_pAll[C_ * C_];            // sum exp(S-10) per (c,e) block
__device__ float         g_pPos[C_];                 // sum of valid diag S values
__device__ int           g_pCnt[C_];                 // count of valid diag entries

// ---------------- K1: bilinear resize (half-pixel, exact) + normsq zeroing ----------------
// grid (16, 8), 256 threads: block handles 512 pixels of image b.
// blockIdx.y==0 blocks also zero g_normsq[b*21..b*21+20] (consumed only after k4a).
__global__ void k1_resize(const int* __restrict__ labels) {
    int b = blockIdx.x;
    if (blockIdx.y == 0 && threadIdx.x < C_)
        g_normsq[b * C_ + threadIdx.x] = 0.0f;

    const int* L = labels + (size_t)b * LW_ * LW_;
    int base = blockIdx.y * 512;
    #pragma unroll
    for (int q = 0; q < 2; q++) {
        int p = base + q * 256 + threadIdx.x;
        int y = p >> 6, x = p & 63;
        // src = (i+0.5)*513/64 - 0.5 ; exact in fp32 (multiples of 1/128)
        float sy = (y + 0.5f) * 8.015625f - 0.5f;
        float sx = (x + 0.5f) * 8.015625f - 0.5f;
        int y0 = (int)sy; float wy = sy - (float)y0;
        int x0 = (int)sx; float wx = sx - (float)x0;
        const int* r0 = L + y0 * LW_ + x0;
        const int* r1 = r0 + LW_;
        float v00 = (float)r0[0], v01 = (float)r0[1];
        float v10 = (float)r1[0], v11 = (float)r1[1];
        float v = (1.0f - wy) * ((1.0f - wx) * v00 + wx * v01)
                +          wy * ((1.0f - wx) * v10 + wx * v11);
        int c = (int)v;   // truncation; v exact
        g_lab[b * HW_ + p] = (unsigned char)c;
    }
}

// ---------------- K2: masked per-class pooling (the 134 MB pass) ----------------
// grid (16, 64), 256 threads; warp w handles channel d = dt*8 + w, fully independent.
__global__ __launch_bounds__(256) void k2_pool(const float* __restrict__ feat) {
    int b   = blockIdx.x;
    int dt  = blockIdx.y;
    int tid = threadIdx.x;
    int w = tid >> 5, lane = tid & 31;

    __shared__ unsigned char slab[HW_];
    __shared__ float bins[8 * C_ * 32];

    ((uint4*)slab)[tid] = ((const uint4*)(g_lab + b * HW_))[tid];
    __syncthreads();

    int d = dt * 8 + w;
    float* bw = bins + w * (C_ * 32);

    #pragma unroll
    for (int c = 0; c < C_; c++) bw[c * 32 + lane] = 0.0f;

    const float4* F = (const float4*)(feat + ((size_t)(b * D_ + d)) * HW_);
    #pragma unroll 8
    for (int k = 0; k < 32; k++) {
        int p4 = k * 32 + lane;
        float4 f = __ldcs(&F[p4]);
        uchar4 lc = ((const uchar4*)slab)[p4];
        bw[lc.x * 32 + lane] += f.x;
        bw[lc.y * 32 + lane] += f.y;
        bw[lc.z * 32 + lane] += f.z;
        bw[lc.w * 32 + lane] += f.w;
    }
    __syncwarp();

    // lane c (<21) sums class c's 32 columns; XOR-rotated reads -> conflict-free
    if (lane < C_) {
        float s = 0.0f;
        #pragma unroll
        for (int m = 0; m < 32; m++)
            s += bw[lane * 32 + ((m + lane) & 31)];
        g_sums[((size_t)(b * C_ + lane)) * D_ + d] = s;
    }
}

// ---------------- K4a: partial Gram SGEMM  U_z = S_z * S_z^T ----------------
// grid (11,11,2), 128 threads. 32x32 tile, 4x2 per thread, K chunk = 256 (2 stages).
// Diagonal tiles accumulate squared norms into g_normsq (2-way fp atomics: commutative).
__global__ __launch_bounds__(128) void k4a_gemm() {
    __shared__ float4 As4[32][32];   // [row][k4]
    __shared__ float4 Bs4[32][32];   // [k4][col]

    int t = threadIdx.x;
    int tr = t >> 4;
    int tc = t & 15;
    int rowBase = blockIdx.y * 32;
    int colBase = blockIdx.x * 32;
    int kz = blockIdx.z;

    float acc[4][2];
    #pragma unroll
    for (int r = 0; r < 4; r++) { acc[r][0] = 0.f; acc[r][1] = 0.f; }

    const float4* P4 = (const float4*)g_sums;   // row stride 128 f4

    #pragma unroll
    for (int kc = 0; kc < 2; kc++) {
        int kOff = kz * 64 + kc * 32;
        #pragma unroll
        for (int m = 0; m < 8; m++) {
            int idx = m * 128 + t;
            int row = idx >> 5, q = idx & 31;
            int v = rowBase + row;
            As4[row][q] = (v < NV_) ? P4[(size_t)v * 128 + kOff + q]
                                    : make_float4(0.f, 0.f, 0.f, 0.f);
        }
        #pragma unroll
        for (int m = 0; m < 8; m++) {
            int idx = m * 128 + t;
            int row = idx >> 5, q = idx & 31;
            int v = colBase + row;
            Bs4[q][row] = (v < NV_) ? P4[(size_t)v * 128 + kOff + q]
                                    : make_float4(0.f, 0.f, 0.f, 0.f);
        }
        __syncthreads();

        #pragma unroll 8
        for (int k4 = 0; k4 < 32; k4++) {
            float4 b0 = Bs4[k4][tc];
            float4 b1 = Bs4[k4][tc + 16];
            #pragma unroll
            for (int r = 0; r < 4; r++) {
                float4 a = As4[tr * 4 + r][k4];
                acc[r][0] = fmaf(a.x, b0.x, fmaf(a.y, b0.y, fmaf(a.z, b0.z, fmaf(a.w, b0.w, acc[r][0]))));
                acc[r][1] = fmaf(a.x, b1.x, fmaf(a.y, b1.y, fmaf(a.z, b1.z, fmaf(a.w, b1.w, acc[r][1]))));
            }
        }
        __syncthreads();
    }

    float* out = g_Spart + (size_t)kz * GR_ * GR_;
    #pragma unroll
    for (int r = 0; r < 4; r++) {
        int v = rowBase + tr * 4 + r;
        out[(size_t)v * GR_ + colBase + tc]      = acc[r][0];
        out[(size_t)v * GR_ + colBase + tc + 16] = acc[r][1];
    }

    if (rowBase == colBase) {
        #pragma unroll
        for (int r = 0; r < 4; r++) {
            int rl = tr * 4 + r;
            int v = rowBase + rl;
            if (v < NV_) {
                if (rl == tc)      atomicAdd(&g_normsq[v], acc[r][0]);
                if (rl == tc + 16) atomicAdd(&g_normsq[v], acc[r][1]);
            }
        }
    }
}

// ---------------- K4b: per-(c,e) block exp-sum reduce ----------------
// validity derived from normsq > 0 (class absent <=> pooled sum identically 0)
__global__ __launch_bounds__(256) void k4b_reduce() {
    int c = blockIdx.x / C_;
    int e = blockIdx.x % C_;
    int tid = threadIdx.x;
    int i = tid >> 4;
    int j = tid & 15;
    int vi = i * C_ + c, vj = j * C_ + e;

    float u = g_Spart[(size_t)vi * GR_ + vj]
            + g_Spart[(size_t)GR_ * GR_ + (size_t)vi * GR_ + vj];
    float nsqi = g_normsq[vi];
    float nsqj = g_normsq[vj];
    float rni = 1.0f / fmaxf(sqrtf(nsqi), 1e-12f);
    float rnj = 1.0f / fmaxf(sqrtf(nsqj), 1e-12f);
    float dot = u * rni * rnj;

    bool valid = (nsqi > 0.0f) && (nsqj > 0.0f);
    float s    = dot * 10.0f;                       // / T
    float term = valid ? expf(s - 10.0f) : 0.0f;    // shift by 1/T (max possible)

    #pragma unroll
    for (int o = 16; o > 0; o >>= 1)
        term += __shfl_xor_sync(0xffffffffu, term, o);

    __shared__ float wt[8], wp[8], wc[8];
    int warp = tid >> 5;
    bool diagBlk = (e == c);                        // uniform per block

    if (diagBlk) {
        float pos  = valid ? s : 0.0f;
        float cntv = valid ? 1.0f : 0.0f;
        #pragma unroll
        for (int o = 16; o > 0; o >>= 1) {
            pos  += __shfl_xor_sync(0xffffffffu, pos, o);
            cntv += __shfl_xor_sync(0xffffffffu, cntv, o);
        }
        if ((tid & 31) == 0) { wp[warp] = pos; wc[warp] = cntv; }
    }
    if ((tid & 31) == 0) wt[warp] = term;
    __syncthreads();
    if (tid == 0) {
        float T = 0.f;
        #pragma unroll
        for (int w = 0; w < 8; w++) T += wt[w];
        g_pAll[blockIdx.x] = T;
        if (diagBlk) {
            float P = 0.f, Cn = 0.f;
            #pragma unroll
            for (int w = 0; w < 8; w++) { P += wp[w]; Cn += wc[w]; }
            g_pPos[c] = P; g_pCnt[c] = (int)(Cn + 0.5f);
        }
    }
}

// ---------------- K5: per-class loss + total ----------------
__global__ void k5_final(float* __restrict__ out) {
    int c = threadIdx.x;
    float loss_c = 0.0f;
    if (c < C_) {
        int cnt = g_pCnt[c];
        if (cnt > 0) {                 // cls_present <=> diag count >= 1
            float sAll = 0.0f;
            #pragma unroll
            for (int e = 0; e < C_; e++) sAll += g_pAll[c * C_ + e];
            float sDiag = g_pAll[c * C_ + c];
            float lse = 10.0f + logf(sAll + sDiag);
            float pm = g_pPos[c] / (float)(cnt > 1 ? cnt : 1);
            loss_c = lse - pm;
        }
    }
    #pragma unroll
    for (int o = 16; o > 0; o >>= 1) loss_c += __shfl_xor_sync(0xffffffffu, loss_c, o);
    if (threadIdx.x == 0) out[0] = loss_c;
}

// ---------------- launch ----------------
extern "C" void kernel_launch(void* const* d_in, const int* in_sizes, int n_in,
                              void* d_out, int out_size) {
    const float* features = (const float*)d_in[0];   // [16,512,64,64] fp32
    const int*   labels   = (const int*)d_in[1];     // [16,513,513] int32
    float* out = (float*)d_out;

    k1_resize<<<dim3(B_, 8), 256>>>(labels);
    k2_pool<<<dim3(B_, D_ / 8), 256>>>(features);
    k4a_gemm<<<dim3(11, 11, KZ_), 128>>>();
    k4b_reduce<<<C_ * C_, 256>>>();
    k5_final<<<1, 32>>>(out);
}